// round 8
// baseline (speedup 1.0000x reference)
#include <cuda_runtime.h>
#include <cuda_fp16.h>
#include <cuda_bf16.h>

#define MQ 8
#define KQ 4096
#define DG 64
#define NB 32
#define HH 64
#define WW 64
#define H_ITER 16
#define RSTRIDE 36   // uints per smem row (144B): STS.128/LDS.128 aligned
#define QSLOTS (64 * (RSTRIDE / 4) + 16)

// Scratch LUT in fp16: v[m,k,c]  (4 MB). uint4-typed for 16B alignment.
__device__ uint4 g_v4[MQ * KQ * (DG / 8)];

typedef unsigned long long ull;

__device__ __forceinline__ void fma2(ull& d, ull a, ull b) {
    asm("fma.rn.f32x2 %0, %1, %2, %3;" : "=l"(d) : "l"(a), "l"(b), "l"(d));
}

// ---------------------------------------------------------------------------
// Phase 1: per-m GEMM  v[m, k, c] = codebook[m,k,:] . wv[m,c,:]  (fp16 out)
// ---------------------------------------------------------------------------
__global__ __launch_bounds__(128) void compute_v_kernel(
    const float* __restrict__ codebook,   // [M, K, DG]
    const float* __restrict__ wv)         // [M, DG(c), DG(d)]
{
    __shared__ float cb_s[64 * 66];
    __shared__ float wv_s[64 * 66];

    const int m  = blockIdx.y;
    const int k0 = blockIdx.x * 64;
    const int tid = threadIdx.x;

    const float4* cb4 = reinterpret_cast<const float4*>(
        codebook + ((long)m * KQ + k0) * DG);
    const float4* wv4 = reinterpret_cast<const float4*>(wv + m * 64 * 64);
    #pragma unroll
    for (int it = 0; it < 8; it++) {
        int idx = tid + it * 128;
        int r = idx >> 4, d = (idx & 15) * 4;
        float4 a = cb4[idx];
        cb_s[r * 66 + d + 0] = a.x; cb_s[r * 66 + d + 1] = a.y;
        cb_s[r * 66 + d + 2] = a.z; cb_s[r * 66 + d + 3] = a.w;
        float4 b = wv4[idx];
        wv_s[r * 66 + d + 0] = b.x; wv_s[r * 66 + d + 1] = b.y;
        wv_s[r * 66 + d + 2] = b.z; wv_s[r * 66 + d + 3] = b.w;
    }
    __syncthreads();

    const int kt = tid >> 4;
    const int ct = tid & 15;

    const ull* cbp = reinterpret_cast<const ull*>(cb_s) + (kt * 8) * 33;
    const ull* wvp = reinterpret_cast<const ull*>(wv_s) + ct * 33;

    ull acc[8][4];
    #pragma unroll
    for (int i = 0; i < 8; i++)
        #pragma unroll
        for (int j = 0; j < 4; j++) acc[i][j] = 0ull;

    #pragma unroll 2
    for (int d2 = 0; d2 < 32; d2++) {
        ull b[4];
        #pragma unroll
        for (int j = 0; j < 4; j++) b[j] = wvp[j * 16 * 33 + d2];
        #pragma unroll
        for (int i = 0; i < 8; i++) {
            ull a = cbp[i * 33 + d2];
            fma2(acc[i][0], a, b[0]);
            fma2(acc[i][1], a, b[1]);
            fma2(acc[i][2], a, b[2]);
            fma2(acc[i][3], a, b[3]);
        }
    }

    __half* gvh = reinterpret_cast<__half*>(g_v4);
    #pragma unroll
    for (int i = 0; i < 8; i++) {
        int k = k0 + kt * 8 + i;
        __half* dst = gvh + ((unsigned)(m * KQ + k)) * DG;
        #pragma unroll
        for (int j = 0; j < 4; j++) {
            float2 p = *reinterpret_cast<float2*>(&acc[i][j]);
            dst[ct + 16 * j] = __float2half(p.x + p.y);
        }
    }
}

// ---------------------------------------------------------------------------
// Phase 2: pipelined gather (fp16 LUT) + transpose scatter.
// bid = [n(5) | hg(2) | m(3)]: m in LOW bits -> same-SM CTAs (stride ~148,
// 148 mod 8 = 4) share m in {a, a^4} -> better L1 residency of the LUT.
// Double-buffered smem tile, ONE __syncthreads per h-row.
// ---------------------------------------------------------------------------
__global__ __launch_bounds__(256) void gather_kernel(
    const int* __restrict__ codes,   // [N, H, W, M]
    float* __restrict__ out)         // [N, M*DG, H, W]
{
    __shared__ int  codes_s[H_ITER * 64];
    __shared__ uint4 vsq[2][QSLOTS];   // ping-pong tiles

    const unsigned bid = blockIdx.x;     // [n(5) | hg(2) | m(3)]
    const unsigned m  = bid & 7;
    const unsigned hg = (bid >> 3) & 3;
    const unsigned n  = bid >> 5;
    const unsigned tid = threadIdx.x;
    const unsigned h0 = hg * H_ITER;

    // Load codes for the whole h-group once.
    #pragma unroll
    for (int i = tid; i < H_ITER * 64; i += 256) {
        unsigned hh = (unsigned)i >> 6, w = (unsigned)i & 63;
        codes_s[i] = __ldg(&codes[((n * HH + h0 + hh) * WW + w) * MQ + m]);
    }
    __syncthreads();

    // Load mapping: q = uint4-slot (0..7) in the 128B fp16 row; rows rw, rw+32.
    const unsigned q  = tid & 7;
    const unsigned rw = tid >> 3;            // 0..31
    const uint4* gv = g_v4;
    const unsigned mbase = m * (KQ * 8u);    // uint4 units

    // Store-phase mapping
    const unsigned w  = tid & 63;
    const unsigned cb = tid >> 6;            // 0..3 -> c in [cb*16, cb*16+16)
    float* outb = out + (unsigned)((n * 512u + m * 64u) * 4096u) + w;
    const unsigned wsw = 2u * (w & 3);       // slot swizzle for row w
    const unsigned lbase = w * (RSTRIDE / 4);

    const unsigned s0 = rw * RSTRIDE / 4 + (q ^ (2u * (rw & 3)));
    const unsigned s1 = (rw + 32) * RSTRIDE / 4 + (q ^ (2u * (rw & 3)));

    uint4 r0v, r1v;
    // Prefetch + stage tile 0 into buffer 0
    {
        unsigned c0 = (unsigned)codes_s[rw];
        unsigned c1 = (unsigned)codes_s[rw + 32];
        r0v = __ldg(&gv[mbase + c0 * 8 + q]);
        r1v = __ldg(&gv[mbase + c1 * 8 + q]);
        vsq[0][s0] = r0v;
        vsq[0][s1] = r1v;
    }
    __syncthreads();

    #pragma unroll
    for (int h = 0; h < H_ITER; h++) {
        const unsigned buf = (unsigned)h & 1u;

        // Prefetch tile h+1 (regs) — latency covered by the store phase.
        if (h + 1 < H_ITER) {
            unsigned c0 = (unsigned)codes_s[(h + 1) * 64 + rw];
            unsigned c1 = (unsigned)codes_s[(h + 1) * 64 + rw + 32];
            r0v = __ldg(&gv[mbase + c0 * 8 + q]);
            r1v = __ldg(&gv[mbase + c1 * 8 + q]);
        }

        // Store phase: 2 swizzled LDS.128 -> cvt -> 16 coalesced STG.32.
        float* outp = outb + (h0 + (unsigned)h) * WW;
        #pragma unroll
        for (int sl = 0; sl < 2; sl++) {
            unsigned slot = (2u * cb + (unsigned)sl) ^ wsw;
            uint4 u = vsq[buf][lbase + slot];
            unsigned c0 = cb * 16 + (unsigned)sl * 8;
            float2 f;
            f = __half22float2(*reinterpret_cast<__half2*>(&u.x));
            __stcs(&outp[(c0 + 0) * 4096u], f.x);
            __stcs(&outp[(c0 + 1) * 4096u], f.y);
            f = __half22float2(*reinterpret_cast<__half2*>(&u.y));
            __stcs(&outp[(c0 + 2) * 4096u], f.x);
            __stcs(&outp[(c0 + 3) * 4096u], f.y);
            f = __half22float2(*reinterpret_cast<__half2*>(&u.z));
            __stcs(&outp[(c0 + 4) * 4096u], f.x);
            __stcs(&outp[(c0 + 5) * 4096u], f.y);
            f = __half22float2(*reinterpret_cast<__half2*>(&u.w));
            __stcs(&outp[(c0 + 6) * 4096u], f.x);
            __stcs(&outp[(c0 + 7) * 4096u], f.y);
        }

        // Stage tile h+1 into the other buffer.
        if (h + 1 < H_ITER) {
            vsq[buf ^ 1u][s0] = r0v;
            vsq[buf ^ 1u][s1] = r1v;
        }
        __syncthreads();
    }
}

extern "C" void kernel_launch(void* const* d_in, const int* in_sizes, int n_in,
                              void* d_out, int out_size)
{
    const int*   codes    = (const int*)d_in[0];    // (32,64,64,8) int32
    const float* codebook = (const float*)d_in[1];  // (8,4096,64) fp32
    const float* wv       = (const float*)d_in[2];  // (8,64,64) fp32
    float*       out      = (float*)d_out;          // (32,512,64,64) fp32

    (void)in_sizes; (void)n_in; (void)out_size;

    dim3 g1(KQ / 64, MQ);
    compute_v_kernel<<<g1, 128>>>(codebook, wv);

    // 1024 blocks: [n(5) | hg(2) | m(3)]
    gather_kernel<<<NB * MQ * (HH / H_ITER), 256>>>(codes, out);
}

// round 9
// speedup vs baseline: 1.5057x; 1.5057x over previous
#include <cuda_runtime.h>
#include <cuda_fp16.h>
#include <cuda_bf16.h>

#define MQ 8
#define KQ 4096
#define DG 64
#define NB 32
#define HH 64
#define WW 64
#define H_ITER 8
#define RSTRIDE 36   // uints per smem row (144B): STS.128/LDS.128 aligned
#define QSLOTS (64 * (RSTRIDE / 4) + 16)

// Scratch LUT in fp16: v[m,k,c]  (4 MB). uint4-typed for 16B alignment.
__device__ uint4 g_v4[MQ * KQ * (DG / 8)];

typedef unsigned long long ull;

__device__ __forceinline__ void fma2(ull& d, ull a, ull b) {
    asm("fma.rn.f32x2 %0, %1, %2, %3;" : "=l"(d) : "l"(a), "l"(b), "l"(d));
}

// ---------------------------------------------------------------------------
// Phase 1: per-m GEMM  v[m, k, c] = codebook[m,k,:] . wv[m,c,:]  (fp16 out)
// R7-proven: 64 k-tile, packed f32x2 FMA.
// ---------------------------------------------------------------------------
__global__ __launch_bounds__(128) void compute_v_kernel(
    const float* __restrict__ codebook,   // [M, K, DG]
    const float* __restrict__ wv)         // [M, DG(c), DG(d)]
{
    __shared__ float cb_s[64 * 66];
    __shared__ float wv_s[64 * 66];

    const int m  = blockIdx.y;
    const int k0 = blockIdx.x * 64;
    const int tid = threadIdx.x;

    const float4* cb4 = reinterpret_cast<const float4*>(
        codebook + ((long)m * KQ + k0) * DG);
    const float4* wv4 = reinterpret_cast<const float4*>(wv + m * 64 * 64);
    #pragma unroll
    for (int it = 0; it < 8; it++) {
        int idx = tid + it * 128;
        int r = idx >> 4, d = (idx & 15) * 4;
        float4 a = cb4[idx];
        cb_s[r * 66 + d + 0] = a.x; cb_s[r * 66 + d + 1] = a.y;
        cb_s[r * 66 + d + 2] = a.z; cb_s[r * 66 + d + 3] = a.w;
        float4 b = wv4[idx];
        wv_s[r * 66 + d + 0] = b.x; wv_s[r * 66 + d + 1] = b.y;
        wv_s[r * 66 + d + 2] = b.z; wv_s[r * 66 + d + 3] = b.w;
    }
    __syncthreads();

    const int kt = tid >> 4;
    const int ct = tid & 15;

    const ull* cbp = reinterpret_cast<const ull*>(cb_s) + (kt * 8) * 33;
    const ull* wvp = reinterpret_cast<const ull*>(wv_s) + ct * 33;

    ull acc[8][4];
    #pragma unroll
    for (int i = 0; i < 8; i++)
        #pragma unroll
        for (int j = 0; j < 4; j++) acc[i][j] = 0ull;

    #pragma unroll 2
    for (int d2 = 0; d2 < 32; d2++) {
        ull b[4];
        #pragma unroll
        for (int j = 0; j < 4; j++) b[j] = wvp[j * 16 * 33 + d2];
        #pragma unroll
        for (int i = 0; i < 8; i++) {
            ull a = cbp[i * 33 + d2];
            fma2(acc[i][0], a, b[0]);
            fma2(acc[i][1], a, b[1]);
            fma2(acc[i][2], a, b[2]);
            fma2(acc[i][3], a, b[3]);
        }
    }

    __half* gvh = reinterpret_cast<__half*>(g_v4);
    #pragma unroll
    for (int i = 0; i < 8; i++) {
        int k = k0 + kt * 8 + i;
        __half* dst = gvh + ((unsigned)(m * KQ + k)) * DG;
        #pragma unroll
        for (int j = 0; j < 4; j++) {
            float2 p = *reinterpret_cast<float2*>(&acc[i][j]);
            dst[ct + 16 * j] = __float2half(p.x + p.y);
        }
    }
}

// ---------------------------------------------------------------------------
// Phase 2: pipelined gather (fp16 LUT) + transpose scatter.
// 128-thread blocks (4 warps): ~2x more independent CTAs/SM -> barrier
// domains decouple, L1 pipe stays fed. bid = [n(5) | m(3) | hg(3)] (R7 order).
// Per thread: 4 LDG.128 in flight, 4 STS.128, 4 LDS.128, 32 STG.32.
// ---------------------------------------------------------------------------
__global__ __launch_bounds__(128) void gather_kernel(
    const int* __restrict__ codes,   // [N, H, W, M]
    float* __restrict__ out)         // [N, M*DG, H, W]
{
    __shared__ int  codes_s[H_ITER * 64];
    __shared__ uint4 vsq[QSLOTS];     // 64 rows x 9 uint4-slots + pad

    const unsigned bid = blockIdx.x;     // [n(5) | m(3) | hg(3)]
    const unsigned hg = bid & 7;
    const unsigned m  = (bid >> 3) & 7;
    const unsigned n  = bid >> 6;
    const unsigned tid = threadIdx.x;
    const unsigned h0 = hg * H_ITER;

    // Load codes for the whole h-group once (4 per thread).
    #pragma unroll
    for (int i = tid; i < H_ITER * 64; i += 128) {
        unsigned hh = (unsigned)i >> 6, w = (unsigned)i & 63;
        codes_s[i] = __ldg(&codes[((n * HH + h0 + hh) * WW + w) * MQ + m]);
    }
    __syncthreads();

    // Load mapping: q = uint4-slot (0..7); rows rw + 16*i, i = 0..3.
    const unsigned q  = tid & 7;
    const unsigned rw = tid >> 3;            // 0..15
    const uint4* gv = g_v4;
    const unsigned mbase = m * (KQ * 8u);    // uint4 units
    const unsigned qsw = q ^ (2u * (rw & 3)); // rows rw+16i share (row&3)

    // Store-phase mapping: w = tid&63, cb2 = tid>>6 -> 32 channels each.
    const unsigned w   = tid & 63;
    const unsigned cb2 = tid >> 6;           // 0..1
    float* outb = out + (unsigned)((n * 512u + m * 64u) * 4096u) + w;
    const unsigned wsw = 2u * (w & 3);
    const unsigned lbase = w * (RSTRIDE / 4);

    unsigned s[4];
    #pragma unroll
    for (int i = 0; i < 4; i++)
        s[i] = (rw + 16u * i) * (RSTRIDE / 4) + qsw;

    uint4 r[4];
    // Prefetch tile 0
    #pragma unroll
    for (int i = 0; i < 4; i++) {
        unsigned code = (unsigned)codes_s[rw + 16 * i];
        r[i] = __ldg(&gv[mbase + code * 8 + q]);
    }

    #pragma unroll 2
    for (int h = 0; h < H_ITER; h++) {
        // STS current tile (swizzled STS.128, conflict-free).
        #pragma unroll
        for (int i = 0; i < 4; i++) vsq[s[i]] = r[i];
        __syncthreads();

        // Prefetch next tile — consumed only after the store phase.
        if (h + 1 < H_ITER) {
            #pragma unroll
            for (int i = 0; i < 4; i++) {
                unsigned code = (unsigned)codes_s[(h + 1) * 64 + rw + 16 * i];
                r[i] = __ldg(&gv[mbase + code * 8 + q]);
            }
        }

        // Store phase: 4 swizzled LDS.128 -> cvt -> 32 coalesced STG.32.
        float* outp = outb + (h0 + (unsigned)h) * WW;
        #pragma unroll
        for (int sl = 0; sl < 4; sl++) {
            unsigned slot = (4u * cb2 + (unsigned)sl) ^ wsw;
            uint4 u = vsq[lbase + slot];
            unsigned c0 = cb2 * 32 + (unsigned)sl * 8;
            float2 f;
            f = __half22float2(*reinterpret_cast<__half2*>(&u.x));
            __stcs(&outp[(c0 + 0) * 4096u], f.x);
            __stcs(&outp[(c0 + 1) * 4096u], f.y);
            f = __half22float2(*reinterpret_cast<__half2*>(&u.y));
            __stcs(&outp[(c0 + 2) * 4096u], f.x);
            __stcs(&outp[(c0 + 3) * 4096u], f.y);
            f = __half22float2(*reinterpret_cast<__half2*>(&u.z));
            __stcs(&outp[(c0 + 4) * 4096u], f.x);
            __stcs(&outp[(c0 + 5) * 4096u], f.y);
            f = __half22float2(*reinterpret_cast<__half2*>(&u.w));
            __stcs(&outp[(c0 + 6) * 4096u], f.x);
            __stcs(&outp[(c0 + 7) * 4096u], f.y);
        }
        __syncthreads();
    }
}

extern "C" void kernel_launch(void* const* d_in, const int* in_sizes, int n_in,
                              void* d_out, int out_size)
{
    const int*   codes    = (const int*)d_in[0];    // (32,64,64,8) int32
    const float* codebook = (const float*)d_in[1];  // (8,4096,64) fp32
    const float* wv       = (const float*)d_in[2];  // (8,64,64) fp32
    float*       out      = (float*)d_out;          // (32,512,64,64) fp32

    (void)in_sizes; (void)n_in; (void)out_size;

    dim3 g1(KQ / 64, MQ);
    compute_v_kernel<<<g1, 128>>>(codebook, wv);

    // 32 * 8 * 8 = 2048 blocks of 128 threads
    gather_kernel<<<NB * MQ * (HH / H_ITER), 128>>>(codes, out);
}